// round 15
// baseline (speedup 1.0000x reference)
#include <cuda_runtime.h>
#include <math.h>

// Problem dims
#define TT   512
#define BB   256
#define OBSD 128
#define ACTD 32
#define IND  160
#define HIDD 512
#define G3D  1536
#define HFD  512

static constexpr size_t TBn = (size_t)TT * BB;      // 131072
static constexpr int NBLK = 2048;                    // reduction blocks per sum

// -------- scratch (static device globals; no runtime allocation) ----------
__device__ float g_GI [TBn * G3D];   // [T*B, 1536] input-gate preacts
__device__ float g_GI0[BB  * G3D];   // step-0 preacts
__device__ float g_HS [TBn * HIDD];  // emitted hidden states
__device__ float g_part[3 * NBLK];   // loss partials

// monotonic barrier counter (zeroed by gate0_k each call -> graph-replay safe)
__device__ unsigned g_rcnt;

__device__ __forceinline__ float4 ldg4(const float* p) {
    return *reinterpret_cast<const float4*>(p);
}
__device__ __forceinline__ float sigmoidf_(float x) { return 1.f / (1.f + expf(-x)); }

// ---- packed fp32x2 helpers ----
__device__ __forceinline__ unsigned long long pk2(float lo, float hi) {
    unsigned long long r;
    asm("mov.b64 %0, {%1, %2};" : "=l"(r) : "f"(lo), "f"(hi));
    return r;
}
__device__ __forceinline__ void fma2(unsigned long long& d,
                                     unsigned long long a, unsigned long long b) {
    asm("fma.rn.f32x2 %0, %1, %2, %0;" : "+l"(d) : "l"(a), "l"(b));
}
__device__ __forceinline__ float2 upk2(unsigned long long v) {
    float2 f;
    asm("mov.b64 {%0, %1}, %2;" : "=f"(f.x), "=f"(f.y) : "l"(v));
    return f;
}

// ---------------------------------------------------------------------------
// Generic tiled SGEMM with f32x2 inner loop (measured at the fp32 roofline).
// ---------------------------------------------------------------------------
template<int BM, int BN, int BK, int TM, int TN, int ACTMODE, bool CONCAT>
__global__ void __launch_bounds__((BM / TM) * (BN / TN))
sgemm_k(const float* __restrict__ A, int ldA,
        const float* __restrict__ A2,
        const float* __restrict__ W, int ldW,
        const float* __restrict__ bias,
        float* __restrict__ C, int ldC,
        int K)
{
    constexpr int NT = (BM / TM) * (BN / TN);
    constexpr int KQ = BK / 4;
    constexpr int TNP = TN / 2;

    __shared__ __align__(16) float As[BK][BM + 4];
    __shared__ __align__(16) float Ws[BK][BN + 4];

    const int tid = threadIdx.x;
    const int tx  = tid % (BN / TN);
    const int ty  = tid / (BN / TN);
    const int m0  = blockIdx.y * BM;
    const int n0  = blockIdx.x * BN;

    unsigned long long acc2[TM][TNP];
#pragma unroll
    for (int i = 0; i < TM; i++)
#pragma unroll
        for (int j = 0; j < TNP; j++) acc2[i][j] = 0ull;

    for (int k0 = 0; k0 < K; k0 += BK) {
        for (int i4 = tid; i4 < BM * KQ; i4 += NT) {
            int m = i4 / KQ, q = i4 % KQ;
            int kg = k0 + q * 4;
            float4 v;
            if (CONCAT) {
                if (kg < OBSD) v = ldg4(A  + (size_t)(m0 + m) * OBSD + kg);
                else           v = ldg4(A2 + (size_t)(m0 + m) * ACTD + (kg - OBSD));
            } else {
                v = ldg4(A + (size_t)(m0 + m) * ldA + kg);
            }
            As[q * 4 + 0][m] = v.x; As[q * 4 + 1][m] = v.y;
            As[q * 4 + 2][m] = v.z; As[q * 4 + 3][m] = v.w;
        }
        for (int i4 = tid; i4 < BN * KQ; i4 += NT) {
            int n = i4 / KQ, q = i4 % KQ;
            int kg = k0 + q * 4;
            float4 v = ldg4(W + (size_t)(n0 + n) * ldW + kg);
            Ws[q * 4 + 0][n] = v.x; Ws[q * 4 + 1][n] = v.y;
            Ws[q * 4 + 2][n] = v.z; Ws[q * 4 + 3][n] = v.w;
        }
        __syncthreads();

#pragma unroll
        for (int kk = 0; kk < BK; kk++) {
            float a[TM];
#pragma unroll
            for (int i = 0; i < TM; i += 4)
                *reinterpret_cast<float4*>(&a[i]) =
                    *reinterpret_cast<const float4*>(&As[kk][ty * TM + i]);
            unsigned long long b2[TNP];
#pragma unroll
            for (int j = 0; j < TNP; j += 2) {
                ulonglong2 t = *reinterpret_cast<const ulonglong2*>(&Ws[kk][tx * TN + 2 * j]);
                b2[j] = t.x; b2[j + 1] = t.y;
            }
#pragma unroll
            for (int i = 0; i < TM; i++) {
                unsigned long long ad = pk2(a[i], a[i]);
#pragma unroll
                for (int j = 0; j < TNP; j++) fma2(acc2[i][j], ad, b2[j]);
            }
        }
        __syncthreads();
    }

#pragma unroll
    for (int i = 0; i < TM; i++) {
        size_t m = (size_t)m0 + ty * TM + i;
#pragma unroll
        for (int j = 0; j < TNP; j++) {
            float2 v2 = upk2(acc2[i][j]);
            int n = n0 + tx * TN + 2 * j;
            float v = v2.x + bias[n];
            float w = v2.y + bias[n + 1];
            if (ACTMODE == 1) {
                v = (v > 0.f) ? v : expm1f(v);
                w = (w > 0.f) ? w : expm1f(w);
            }
            C[m * (size_t)ldC + n]     = v;
            C[m * (size_t)ldC + n + 1] = w;
        }
    }
}

// ---------------------------------------------------------------------------
// Persistent GRU recurrence v6: 2 warps per SMSP + zero-mov inner loop.
// 128 CTAs x 256 threads (1 CTA/SM, 8 warps = 2/SMSP).
//   CTA: bg=blockIdx.x>>5 (4 x 64 rows), cg=blockIdx.x&31 (32 x 16 cols).
//   W slice [3][512][16] = 96KB resident in smem all kernel.
//   h_t staged in DUPLICATED layout: Ad[k][2*row] = (h[row][k], h[row][k]),
//   32-k chunks double-buffered (2 x 16KB) -> total smem 128KB.
// Thread tile: 2 rows x 2 cols x 3 gates = 6 FFMA2 per (1 LDS.128 + 3
// LDS.64), NO packing movs: the LDS.128 yields both rows' (a,a) f32x2
// operands directly; W LDS.64 yields the (w0,w1) col-pair operand.
// ONE monotonic grid barrier per step (proven), nanosleep poll.
// ---------------------------------------------------------------------------
#define RNCTA 128

__device__ __forceinline__ void rnn_load_chunk(float* __restrict__ dst,
                                               const float* __restrict__ hp,
                                               int b0, int c, int tid)
{
#pragma unroll
    for (int p = 0; p < 2; p++) {
        int u = p * 256 + tid;
        int row = u & 63, q4 = u >> 6;               // 64 rows x 8 float4 (32 k)
        float4 v = ldg4(hp + (size_t)(b0 + row) * HIDD + c * 32 + q4 * 4);
        float2* d0 = reinterpret_cast<float2*>(&dst[(q4 * 4 + 0) * 128 + 2 * row]);
        float2* d1 = reinterpret_cast<float2*>(&dst[(q4 * 4 + 1) * 128 + 2 * row]);
        float2* d2 = reinterpret_cast<float2*>(&dst[(q4 * 4 + 2) * 128 + 2 * row]);
        float2* d3 = reinterpret_cast<float2*>(&dst[(q4 * 4 + 3) * 128 + 2 * row]);
        *d0 = make_float2(v.x, v.x);
        *d1 = make_float2(v.y, v.y);
        *d2 = make_float2(v.z, v.z);
        *d3 = make_float2(v.w, v.w);
    }
}

__global__ void __launch_bounds__(256)
rnn_k(const float* __restrict__ w_hh, const float* __restrict__ b_hh,
      const float* __restrict__ gi_all, float* __restrict__ hs)
{
    extern __shared__ float sm[];
    float* Wsm  = sm;                    // [3][512][16] = 24576 floats (96KB)
    float* Abuf = sm + 3 * 512 * 16;     // 2 x [32k][128] = 8192 floats (32KB)

    const int tid = threadIdx.x;
    const int bg  = blockIdx.x >> 5;     // 4 groups x 64 rows
    const int cg  = blockIdx.x & 31;     // 32 groups x 16 cols
    const int b0  = bg * 64;
    const int j0  = cg * 16;
    const int tx  = tid & 7;             // 8 col-pairs (16 cols)
    const int ty  = tid >> 3;            // 32 row-pairs (64 rows)

    // one-time: W slice -> smem as [g][k][col] (16-col rows)
    for (int u = tid; u < 3 * 16 * 128; u += 256) {
        int g   = u >> 11;               // 0..2
        int r   = u & 2047;
        int col = r >> 7;                // 0..15
        int kq  = r & 127;               // k = 4*kq
        float4 v = ldg4(w_hh + (size_t)(g * HIDD + j0 + col) * HIDD + kq * 4);
        Wsm[(g * 512 + kq * 4 + 0) * 16 + col] = v.x;
        Wsm[(g * 512 + kq * 4 + 1) * 16 + col] = v.y;
        Wsm[(g * 512 + kq * 4 + 2) * 16 + col] = v.z;
        Wsm[(g * 512 + kq * 4 + 3) * 16 + col] = v.w;
    }
    const int jg = j0 + 2 * tx;
    const int r0 = b0 + 2 * ty;          // this thread's two batch rows: r0, r0+1
    const float2 br = *reinterpret_cast<const float2*>(b_hh + jg);
    const float2 bz = *reinterpret_cast<const float2*>(b_hh + 512 + jg);
    const float2 bn = *reinterpret_cast<const float2*>(b_hh + 1024 + jg);
    __syncthreads();

    for (int t = 0; t < TT - 1; t++) {
        const float* hp = hs + (size_t)t * BB * HIDD;
        float*       ho = hs + (size_t)(t + 1) * BB * HIDD;
        const float* gi = gi_all + (size_t)t * BB * G3D;

        // prefetch gate-phase operands for this thread's 2 rows x 2 cols
        float2 gr_[2], gz_[2], gn_[2], hp_[2];
#pragma unroll
        for (int i = 0; i < 2; i++) {
            const float* gim = gi + (size_t)(r0 + i) * G3D;
            gr_[i] = *reinterpret_cast<const float2*>(gim + jg);
            gz_[i] = *reinterpret_cast<const float2*>(gim + 512 + jg);
            gn_[i] = *reinterpret_cast<const float2*>(gim + 1024 + jg);
            hp_[i] = *reinterpret_cast<const float2*>(
                hp + (size_t)(r0 + i) * HIDD + jg);
        }

        unsigned long long aR[2] = {0,0}, aZ[2] = {0,0}, aN[2] = {0,0};

        rnn_load_chunk(Abuf, hp, b0, 0, tid);
        __syncthreads();
#pragma unroll 1
        for (int c = 0; c < 16; c++) {
            const float* Ac = Abuf + (c & 1) * 4096;
            if (c < 15) rnn_load_chunk(Abuf + ((c + 1) & 1) * 4096, hp, b0, c + 1, tid);
            const float* wR = &Wsm[(0 * 512 + c * 32) * 16 + 2 * tx];
            const float* wZ = &Wsm[(1 * 512 + c * 32) * 16 + 2 * tx];
            const float* wN = &Wsm[(2 * 512 + c * 32) * 16 + 2 * tx];
            const float* Ab = &Ac[4 * ty];
#pragma unroll
            for (int kk = 0; kk < 32; kk++) {
                // (a0,a0,a1,a1) for rows r0, r0+1 — both f32x2 operands ready
                ulonglong2 av = *reinterpret_cast<const ulonglong2*>(Ab + kk * 128);
                unsigned long long r2 = *reinterpret_cast<const unsigned long long*>(wR + kk * 16);
                unsigned long long z2 = *reinterpret_cast<const unsigned long long*>(wZ + kk * 16);
                unsigned long long n2 = *reinterpret_cast<const unsigned long long*>(wN + kk * 16);
                fma2(aR[0], av.x, r2); fma2(aR[1], av.y, r2);
                fma2(aZ[0], av.x, z2); fma2(aZ[1], av.y, z2);
                fma2(aN[0], av.x, n2); fma2(aN[1], av.y, n2);
            }
            __syncthreads();
        }

        // gate math directly on accumulators; store 2 x float2 of h_{t+1}
#pragma unroll
        for (int i = 0; i < 2; i++) {
            float2 vr = upk2(aR[i]), vz = upk2(aZ[i]), vn = upk2(aN[i]);
            float rr0 = sigmoidf_(gr_[i].x + vr.x + br.x);
            float rr1 = sigmoidf_(gr_[i].y + vr.y + br.y);
            float zz0 = sigmoidf_(gz_[i].x + vz.x + bz.x);
            float zz1 = sigmoidf_(gz_[i].y + vz.y + bz.y);
            float nn0 = tanhf    (gn_[i].x + rr0 * (vn.x + bn.x));
            float nn1 = tanhf    (gn_[i].y + rr1 * (vn.y + bn.y));
            float2 hv;
            hv.x = (1.f - zz0) * nn0 + zz0 * hp_[i].x;
            hv.y = (1.f - zz1) * nn1 + zz1 * hp_[i].y;
            *reinterpret_cast<float2*>(ho + (size_t)(r0 + i) * HIDD + jg) = hv;
        }

        // ---- ONE grid barrier per step (monotonic target; nanosleep poll) ----
        __threadfence();
        __syncthreads();
        if (tid == 0) {
            atomicAdd(&g_rcnt, 1u);
            const unsigned target = (unsigned)(RNCTA * (t + 1));
            while (*(volatile unsigned*)&g_rcnt < target) __nanosleep(20);
        }
        __syncthreads();
    }
}

// step 0: h_prev = 0  =>  gh = b_hh,  h0 = (1-z)*n.  Also zeroes the rnn
// barrier counter (runs before rnn_k every call -> graph-replay safe).
__global__ void gate0_k(const float* __restrict__ gi, const float* __restrict__ bhh,
                        float* __restrict__ ho)
{
    if (blockIdx.x == 0 && threadIdx.x == 0) {
        g_rcnt = 0u;
        __threadfence();
    }
    int idx = blockIdx.x * blockDim.x + threadIdx.x;
    int b = idx >> 9, j = idx & 511;
    size_t base = (size_t)b * G3D + j;
    float r = sigmoidf_(gi[base]        + bhh[j]);
    float z = sigmoidf_(gi[base + 512]  + bhh[512 + j]);
    float n = tanhf    (gi[base + 1024] + r * bhh[1024 + j]);
    ho[idx] = (1.f - z) * n;
}

// ---------------------------------------------------------------------------
// N=1 head: one warp per row.
// ---------------------------------------------------------------------------
__global__ void dot_k(const float* __restrict__ A, const float* __restrict__ w,
                      const float* __restrict__ bp, float* __restrict__ out)
{
    int g = blockIdx.x * blockDim.x + threadIdx.x;
    int row = g >> 5, lane = g & 31;
    const float4* a4 = reinterpret_cast<const float4*>(A + (size_t)row * HFD);
    const float4* w4 = reinterpret_cast<const float4*>(w);
    float s = 0.f;
#pragma unroll
    for (int i = lane; i < HFD / 4; i += 32) {
        float4 a = a4[i], b = w4[i];
        s += a.x * b.x + a.y * b.y + a.z * b.z + a.w * b.w;
    }
#pragma unroll
    for (int o = 16; o; o >>= 1) s += __shfl_xor_sync(0xffffffffu, s, o);
    if (lane == 0) out[row] = s + bp[0];
}

// ---------------------------------------------------------------------------
// Loss: deterministic 2-stage sum of squared residuals.
// ---------------------------------------------------------------------------
template<bool BCAST>
__global__ void reduce_sq_k(const float* __restrict__ x, const float* __restrict__ mu,
                            size_t n, float* __restrict__ part)
{
    float s = 0.f;
    for (size_t i = (size_t)blockIdx.x * blockDim.x + threadIdx.x; i < n;
         i += (size_t)gridDim.x * blockDim.x) {
        float m = BCAST ? mu[i >> 5] : mu[i];
        float d = x[i] - m;
        s += d * d;
    }
    __shared__ float sm[256];
    sm[threadIdx.x] = s; __syncthreads();
    for (int o = 128; o; o >>= 1) {
        if (threadIdx.x < o) sm[threadIdx.x] += sm[threadIdx.x + o];
        __syncthreads();
    }
    if (threadIdx.x == 0) part[blockIdx.x] = sm[0];
}

__global__ void finalize_k(const float* __restrict__ part, float* __restrict__ out)
{
    __shared__ double sm[256];
    double s = 0.0;
    for (int i = threadIdx.x; i < 3 * NBLK; i += 256) s += (double)part[i];
    sm[threadIdx.x] = s; __syncthreads();
    for (int o = 128; o; o >>= 1) {
        if (threadIdx.x < o) sm[threadIdx.x] += sm[threadIdx.x + o];
        __syncthreads();
    }
    if (threadIdx.x == 0) {
        const double LOG2PI = 1.8378770664093453;
        out[0] = (float)(0.5 * sm[0] / (double)(TT * BB)
                         + 0.5 * LOG2PI * (double)(OBSD + 2 * ACTD));
    }
}

// ---------------------------------------------------------------------------
extern "C" void kernel_launch(void* const* d_in, const int* in_sizes, int n_in,
                              void* d_out, int out_size)
{
    const float* obs    = (const float*)d_in[0];
    const float* action = (const float*)d_in[1];
    /* d_in[2] reward: unused by the reference math */
    const float* w_ih = (const float*)d_in[3];
    const float* w_hh = (const float*)d_in[4];
    const float* b_ih = (const float*)d_in[5];
    const float* b_hh = (const float*)d_in[6];
    const float* ow0 = (const float*)d_in[7],  *ob0 = (const float*)d_in[8];
    const float* ow1 = (const float*)d_in[9],  *ob1 = (const float*)d_in[10];
    const float* ow2 = (const float*)d_in[11], *ob2 = (const float*)d_in[12];
    const float* aw0 = (const float*)d_in[13], *ab0 = (const float*)d_in[14];
    const float* aw1 = (const float*)d_in[15], *ab1 = (const float*)d_in[16];
    const float* aw2 = (const float*)d_in[17], *ab2 = (const float*)d_in[18];
    const float* rw0 = (const float*)d_in[19], *rb0 = (const float*)d_in[20];
    const float* rw1 = (const float*)d_in[21], *rb1 = (const float*)d_in[22];
    const float* rw2 = (const float*)d_in[23], *rb2 = (const float*)d_in[24];

    float *GI, *GI0, *HS, *PART;
    cudaGetSymbolAddress((void**)&GI,   g_GI);
    cudaGetSymbolAddress((void**)&GI0,  g_GI0);
    cudaGetSymbolAddress((void**)&HS,   g_HS);
    cudaGetSymbolAddress((void**)&PART, g_part);
    // MLP scratch aliases the (dead after the recurrence) GI buffer.
    float* F1 = GI;
    float* F2 = GI + TBn * HFD;

    float* out      = (float*)d_out;
    float* pre_obs  = out + 1;
    float* pre_act  = pre_obs + TBn * OBSD;
    float* pre_rew  = pre_act + TBn * ACTD;

    // rnn dynamic smem: 96KB W + 32KB A-dup double buffer = 128KB
    const int rnn_smem = (3 * 512 * 16 + 2 * 32 * 128) * (int)sizeof(float);
    cudaFuncSetAttribute(rnn_k, cudaFuncAttributeMaxDynamicSharedMemorySize, rnn_smem);

    // 1) GI = [obs‖action] @ w_ih^T + b_ih   for all T*B rows
    sgemm_k<128, 128, 8, 8, 8, 0, true><<<dim3(G3D / 128, TBn / 128), 256>>>(
        obs, 0, action, w_ih, IND, b_ih, GI, G3D, IND);

    // 2) GI0 = obs[0] @ w_ih[:, :128]^T + b_ih  (action part of x0 is zero)
    sgemm_k<64, 64, 8, 4, 4, 0, false><<<dim3(G3D / 64, BB / 64), 256>>>(
        obs, OBSD, nullptr, w_ih, IND, b_ih, GI0, G3D, OBSD);

    // 3) h0 -> HS[0]  (also zeroes the rnn barrier counter)
    gate0_k<<<(BB * HIDD) / 256, 256>>>(GI0, b_hh, HS);

    // 4) recurrence: ONE persistent kernel, full-K slices, all 511 steps
    rnn_k<<<RNCTA, 256, rnn_smem>>>(w_hh, b_hh, GI, HS);

    dim3 gH(HFD / 128, TBn / 128);
    dim3 gO(OBSD / 128, TBn / 128);
    dim3 gA(ACTD / 32, TBn / 128);

    // 5) obs head
    sgemm_k<128, 128, 8, 8, 8, 1, false><<<gH, 256>>>(HS, HIDD, nullptr, ow0, HIDD, ob0, F1, HFD, HIDD);
    sgemm_k<128, 128, 8, 8, 8, 1, false><<<gH, 256>>>(F1, HFD, nullptr, ow1, HFD, ob1, F2, HFD, HFD);
    sgemm_k<128, 128, 8, 8, 8, 0, false><<<gO, 256>>>(F2, HFD, nullptr, ow2, HFD, ob2, pre_obs, OBSD, HFD);

    // 6) action head
    sgemm_k<128, 128, 8, 8, 8, 1, false><<<gH, 256>>>(HS, HIDD, nullptr, aw0, HIDD, ab0, F1, HFD, HIDD);
    sgemm_k<128, 128, 8, 8, 8, 1, false><<<gH, 256>>>(F1, HFD, nullptr, aw1, HFD, ab1, F2, HFD, HFD);
    sgemm_k<128, 32, 8, 8, 4, 0, false><<<gA, 128>>>(F2, HFD, nullptr, aw2, HFD, ab2, pre_act, ACTD, HFD);

    // 7) reward head
    sgemm_k<128, 128, 8, 8, 8, 1, false><<<gH, 256>>>(HS, HIDD, nullptr, rw0, HIDD, rb0, F1, HFD, HIDD);
    sgemm_k<128, 128, 8, 8, 8, 1, false><<<gH, 256>>>(F1, HFD, nullptr, rw1, HFD, rb1, F2, HFD, HFD);
    dot_k<<<TBn / 8, 256>>>(F2, rw2, rb2, pre_rew);

    // 8) losses (reward_loss faithfully reproduces the broadcast-vs-action bug)
    reduce_sq_k<false><<<NBLK, 256>>>(obs,    pre_obs, TBn * OBSD, PART);
    reduce_sq_k<false><<<NBLK, 256>>>(action, pre_act, TBn * ACTD, PART + NBLK);
    reduce_sq_k<true ><<<NBLK, 256>>>(action, pre_rew, TBn * ACTD, PART + 2 * NBLK);
    finalize_k<<<1, 256>>>(PART, out);
}

// round 16
// speedup vs baseline: 1.0625x; 1.0625x over previous
#include <cuda_runtime.h>
#include <math.h>

// Problem dims
#define TT   512
#define BB   256
#define OBSD 128
#define ACTD 32
#define IND  160
#define HIDD 512
#define G3D  1536
#define HFD  512

static constexpr size_t TBn = (size_t)TT * BB;      // 131072
static constexpr int NBLK = 2048;                    // reduction blocks per sum

// -------- scratch (static device globals; no runtime allocation) ----------
__device__ float g_GI [TBn * G3D];   // [T*B, 1536] input-gate preacts
__device__ float g_GI0[BB  * G3D];   // step-0 preacts
__device__ float g_HS [TBn * HIDD];  // emitted hidden states
__device__ float g_part[3 * NBLK];   // loss partials

// monotonic barrier counter (zeroed by gate0_k each call -> graph-replay safe)
__device__ unsigned g_rcnt;

__device__ __forceinline__ float4 ldg4(const float* p) {
    return *reinterpret_cast<const float4*>(p);
}
__device__ __forceinline__ float sigmoidf_(float x) { return 1.f / (1.f + expf(-x)); }

// ---- packed fp32x2 helpers ----
__device__ __forceinline__ unsigned long long pk2(float lo, float hi) {
    unsigned long long r;
    asm("mov.b64 %0, {%1, %2};" : "=l"(r) : "f"(lo), "f"(hi));
    return r;
}
__device__ __forceinline__ void fma2(unsigned long long& d,
                                     unsigned long long a, unsigned long long b) {
    asm("fma.rn.f32x2 %0, %1, %2, %0;" : "+l"(d) : "l"(a), "l"(b));
}
__device__ __forceinline__ float2 upk2(unsigned long long v) {
    float2 f;
    asm("mov.b64 {%0, %1}, %2;" : "=f"(f.x), "=f"(f.y) : "l"(v));
    return f;
}

// ---------------------------------------------------------------------------
// Generic tiled SGEMM with f32x2 inner loop (measured at the fp32 roofline).
// ---------------------------------------------------------------------------
template<int BM, int BN, int BK, int TM, int TN, int ACTMODE, bool CONCAT>
__global__ void __launch_bounds__((BM / TM) * (BN / TN))
sgemm_k(const float* __restrict__ A, int ldA,
        const float* __restrict__ A2,
        const float* __restrict__ W, int ldW,
        const float* __restrict__ bias,
        float* __restrict__ C, int ldC,
        int K)
{
    constexpr int NT = (BM / TM) * (BN / TN);
    constexpr int KQ = BK / 4;
    constexpr int TNP = TN / 2;

    __shared__ __align__(16) float As[BK][BM + 4];
    __shared__ __align__(16) float Ws[BK][BN + 4];

    const int tid = threadIdx.x;
    const int tx  = tid % (BN / TN);
    const int ty  = tid / (BN / TN);
    const int m0  = blockIdx.y * BM;
    const int n0  = blockIdx.x * BN;

    unsigned long long acc2[TM][TNP];
#pragma unroll
    for (int i = 0; i < TM; i++)
#pragma unroll
        for (int j = 0; j < TNP; j++) acc2[i][j] = 0ull;

    for (int k0 = 0; k0 < K; k0 += BK) {
        for (int i4 = tid; i4 < BM * KQ; i4 += NT) {
            int m = i4 / KQ, q = i4 % KQ;
            int kg = k0 + q * 4;
            float4 v;
            if (CONCAT) {
                if (kg < OBSD) v = ldg4(A  + (size_t)(m0 + m) * OBSD + kg);
                else           v = ldg4(A2 + (size_t)(m0 + m) * ACTD + (kg - OBSD));
            } else {
                v = ldg4(A + (size_t)(m0 + m) * ldA + kg);
            }
            As[q * 4 + 0][m] = v.x; As[q * 4 + 1][m] = v.y;
            As[q * 4 + 2][m] = v.z; As[q * 4 + 3][m] = v.w;
        }
        for (int i4 = tid; i4 < BN * KQ; i4 += NT) {
            int n = i4 / KQ, q = i4 % KQ;
            int kg = k0 + q * 4;
            float4 v = ldg4(W + (size_t)(n0 + n) * ldW + kg);
            Ws[q * 4 + 0][n] = v.x; Ws[q * 4 + 1][n] = v.y;
            Ws[q * 4 + 2][n] = v.z; Ws[q * 4 + 3][n] = v.w;
        }
        __syncthreads();

#pragma unroll
        for (int kk = 0; kk < BK; kk++) {
            float a[TM];
#pragma unroll
            for (int i = 0; i < TM; i += 4)
                *reinterpret_cast<float4*>(&a[i]) =
                    *reinterpret_cast<const float4*>(&As[kk][ty * TM + i]);
            unsigned long long b2[TNP];
#pragma unroll
            for (int j = 0; j < TNP; j += 2) {
                ulonglong2 t = *reinterpret_cast<const ulonglong2*>(&Ws[kk][tx * TN + 2 * j]);
                b2[j] = t.x; b2[j + 1] = t.y;
            }
#pragma unroll
            for (int i = 0; i < TM; i++) {
                unsigned long long ad = pk2(a[i], a[i]);
#pragma unroll
                for (int j = 0; j < TNP; j++) fma2(acc2[i][j], ad, b2[j]);
            }
        }
        __syncthreads();
    }

#pragma unroll
    for (int i = 0; i < TM; i++) {
        size_t m = (size_t)m0 + ty * TM + i;
#pragma unroll
        for (int j = 0; j < TNP; j++) {
            float2 v2 = upk2(acc2[i][j]);
            int n = n0 + tx * TN + 2 * j;
            float v = v2.x + bias[n];
            float w = v2.y + bias[n + 1];
            if (ACTMODE == 1) {
                v = (v > 0.f) ? v : expm1f(v);
                w = (w > 0.f) ? w : expm1f(w);
            }
            C[m * (size_t)ldC + n]     = v;
            C[m * (size_t)ldC + n + 1] = w;
        }
    }
}

// ---------------------------------------------------------------------------
// Persistent GRU recurrence v7: R15 geometry + explicit software pipelining.
// 128 CTAs x 256 threads (1 CTA/SM, 2 warps/SMSP).
//   CTA: bg=blockIdx.x>>5 (4 x 64 rows), cg=blockIdx.x&31 (32 x 16 cols).
//   W slice [3][512][16] = 96KB resident; h_t staged in DUPLICATED layout
//   Ad[k][2*row]=(h,h), 64-k chunks double-buffered (2 x 32KB) -> 160KB.
// Inner loop: depth-2 register pipeline (load kk+2 operands before kk's
// FFMA2s) to cover the 29-cyc LDS latency.  Chunk staging: LDG->regs at
// loop head, STS only AFTER the FFMA loop (no dependent-STS stall).
// Thread tile: 2 rows x 2 cols x 3 gates = 6 FFMA2/kk, zero packing movs.
// ONE monotonic grid barrier per step, nanosleep poll.
// ---------------------------------------------------------------------------
#define RNCTA 128

__device__ __forceinline__ void rnn_ld_chunk(float4* R, const float* __restrict__ hp,
                                             int b0, int c, int tid)
{
#pragma unroll
    for (int p = 0; p < 4; p++) {
        int u = p * 256 + tid;
        int row = u & 63, q4 = u >> 6;               // 64 rows x 16 float4 (64 k)
        R[p] = ldg4(hp + (size_t)(b0 + row) * HIDD + c * 64 + q4 * 4);
    }
}

__device__ __forceinline__ void rnn_st_chunk(float* __restrict__ dst,
                                             const float4* R, int tid)
{
#pragma unroll
    for (int p = 0; p < 4; p++) {
        int u = p * 256 + tid;
        int row = u & 63, q4 = u >> 6;
        float4 v = R[p];
        *reinterpret_cast<float2*>(&dst[(q4 * 4 + 0) * 128 + 2 * row]) = make_float2(v.x, v.x);
        *reinterpret_cast<float2*>(&dst[(q4 * 4 + 1) * 128 + 2 * row]) = make_float2(v.y, v.y);
        *reinterpret_cast<float2*>(&dst[(q4 * 4 + 2) * 128 + 2 * row]) = make_float2(v.z, v.z);
        *reinterpret_cast<float2*>(&dst[(q4 * 4 + 3) * 128 + 2 * row]) = make_float2(v.w, v.w);
    }
}

__global__ void __launch_bounds__(256)
rnn_k(const float* __restrict__ w_hh, const float* __restrict__ b_hh,
      const float* __restrict__ gi_all, float* __restrict__ hs)
{
    extern __shared__ float sm[];
    float* Wsm  = sm;                    // [3][512][16] = 24576 floats (96KB)
    float* Abuf = sm + 3 * 512 * 16;     // 2 x [64k][128] = 16384 floats (64KB)

    const int tid = threadIdx.x;
    const int bg  = blockIdx.x >> 5;     // 4 groups x 64 rows
    const int cg  = blockIdx.x & 31;     // 32 groups x 16 cols
    const int b0  = bg * 64;
    const int j0  = cg * 16;
    const int tx  = tid & 7;             // 8 col-pairs (16 cols)
    const int ty  = tid >> 3;            // 32 row-pairs (64 rows)

    // one-time: W slice -> smem as [g][k][col] (16-col rows)
    for (int u = tid; u < 3 * 16 * 128; u += 256) {
        int g   = u >> 11;               // 0..2
        int r   = u & 2047;
        int col = r >> 7;                // 0..15
        int kq  = r & 127;               // k = 4*kq
        float4 v = ldg4(w_hh + (size_t)(g * HIDD + j0 + col) * HIDD + kq * 4);
        Wsm[(g * 512 + kq * 4 + 0) * 16 + col] = v.x;
        Wsm[(g * 512 + kq * 4 + 1) * 16 + col] = v.y;
        Wsm[(g * 512 + kq * 4 + 2) * 16 + col] = v.z;
        Wsm[(g * 512 + kq * 4 + 3) * 16 + col] = v.w;
    }
    const int jg = j0 + 2 * tx;
    const int r0 = b0 + 2 * ty;          // this thread's two batch rows
    const float2 br = *reinterpret_cast<const float2*>(b_hh + jg);
    const float2 bz = *reinterpret_cast<const float2*>(b_hh + 512 + jg);
    const float2 bn = *reinterpret_cast<const float2*>(b_hh + 1024 + jg);
    __syncthreads();

    for (int t = 0; t < TT - 1; t++) {
        const float* hp = hs + (size_t)t * BB * HIDD;
        float*       ho = hs + (size_t)(t + 1) * BB * HIDD;
        const float* gi = gi_all + (size_t)t * BB * G3D;

        // prefetch gate-phase operands for this thread's 2 rows x 2 cols
        float2 gr_[2], gz_[2], gn_[2], hp_[2];
#pragma unroll
        for (int i = 0; i < 2; i++) {
            const float* gim = gi + (size_t)(r0 + i) * G3D;
            gr_[i] = *reinterpret_cast<const float2*>(gim + jg);
            gz_[i] = *reinterpret_cast<const float2*>(gim + 512 + jg);
            gn_[i] = *reinterpret_cast<const float2*>(gim + 1024 + jg);
            hp_[i] = *reinterpret_cast<const float2*>(
                hp + (size_t)(r0 + i) * HIDD + jg);
        }

        unsigned long long aR[2] = {0,0}, aZ[2] = {0,0}, aN[2] = {0,0};

        // chunk 0: load regs -> store smem -> sync
        float4 Rs[4];
        rnn_ld_chunk(Rs, hp, b0, 0, tid);
        rnn_st_chunk(Abuf, Rs, tid);
        __syncthreads();

#pragma unroll 1
        for (int c = 0; c < 8; c++) {
            const float* Ac = Abuf + (c & 1) * 8192;
            // issue next chunk's global loads now; STS deferred to loop end
            if (c < 7) rnn_ld_chunk(Rs, hp, b0, c + 1, tid);

            const float* wR = &Wsm[(0 * 512 + c * 64) * 16 + 2 * tx];
            const float* wZ = &Wsm[(1 * 512 + c * 64) * 16 + 2 * tx];
            const float* wN = &Wsm[(2 * 512 + c * 64) * 16 + 2 * tx];
            const float* Ab = &Ac[4 * ty];

            // depth-2 software pipeline over kk
            ulonglong2        av[2];
            unsigned long long wr[2], wz[2], wn[2];
            av[0] = *reinterpret_cast<const ulonglong2*>(Ab);
            wr[0] = *reinterpret_cast<const unsigned long long*>(wR);
            wz[0] = *reinterpret_cast<const unsigned long long*>(wZ);
            wn[0] = *reinterpret_cast<const unsigned long long*>(wN);
            av[1] = *reinterpret_cast<const ulonglong2*>(Ab + 128);
            wr[1] = *reinterpret_cast<const unsigned long long*>(wR + 16);
            wz[1] = *reinterpret_cast<const unsigned long long*>(wZ + 16);
            wn[1] = *reinterpret_cast<const unsigned long long*>(wN + 16);
#pragma unroll
            for (int kk = 0; kk < 64; kk++) {
                const int cur = kk & 1;
                ulonglong2        a  = av[cur];
                unsigned long long r2 = wr[cur], z2 = wz[cur], n2 = wn[cur];
                if (kk < 62) {
                    av[cur] = *reinterpret_cast<const ulonglong2*>(Ab + (kk + 2) * 128);
                    wr[cur] = *reinterpret_cast<const unsigned long long*>(wR + (kk + 2) * 16);
                    wz[cur] = *reinterpret_cast<const unsigned long long*>(wZ + (kk + 2) * 16);
                    wn[cur] = *reinterpret_cast<const unsigned long long*>(wN + (kk + 2) * 16);
                }
                fma2(aR[0], a.x, r2); fma2(aR[1], a.y, r2);
                fma2(aZ[0], a.x, z2); fma2(aZ[1], a.y, z2);
                fma2(aN[0], a.x, n2); fma2(aN[1], a.y, n2);
            }

            if (c < 7) rnn_st_chunk(Abuf + ((c + 1) & 1) * 8192, Rs, tid);
            __syncthreads();
        }

        // gate math directly on accumulators; store 2 x float2 of h_{t+1}
#pragma unroll
        for (int i = 0; i < 2; i++) {
            float2 vr = upk2(aR[i]), vz = upk2(aZ[i]), vn = upk2(aN[i]);
            float rr0 = sigmoidf_(gr_[i].x + vr.x + br.x);
            float rr1 = sigmoidf_(gr_[i].y + vr.y + br.y);
            float zz0 = sigmoidf_(gz_[i].x + vz.x + bz.x);
            float zz1 = sigmoidf_(gz_[i].y + vz.y + bz.y);
            float nn0 = tanhf    (gn_[i].x + rr0 * (vn.x + bn.x));
            float nn1 = tanhf    (gn_[i].y + rr1 * (vn.y + bn.y));
            float2 hv;
            hv.x = (1.f - zz0) * nn0 + zz0 * hp_[i].x;
            hv.y = (1.f - zz1) * nn1 + zz1 * hp_[i].y;
            *reinterpret_cast<float2*>(ho + (size_t)(r0 + i) * HIDD + jg) = hv;
        }

        // ---- ONE grid barrier per step (monotonic target; nanosleep poll) ----
        __threadfence();
        __syncthreads();
        if (tid == 0) {
            atomicAdd(&g_rcnt, 1u);
            const unsigned target = (unsigned)(RNCTA * (t + 1));
            while (*(volatile unsigned*)&g_rcnt < target) __nanosleep(20);
        }
        __syncthreads();
    }
}

// step 0: h_prev = 0  =>  gh = b_hh,  h0 = (1-z)*n.  Also zeroes the rnn
// barrier counter (runs before rnn_k every call -> graph-replay safe).
__global__ void gate0_k(const float* __restrict__ gi, const float* __restrict__ bhh,
                        float* __restrict__ ho)
{
    if (blockIdx.x == 0 && threadIdx.x == 0) {
        g_rcnt = 0u;
        __threadfence();
    }
    int idx = blockIdx.x * blockDim.x + threadIdx.x;
    int b = idx >> 9, j = idx & 511;
    size_t base = (size_t)b * G3D + j;
    float r = sigmoidf_(gi[base]        + bhh[j]);
    float z = sigmoidf_(gi[base + 512]  + bhh[512 + j]);
    float n = tanhf    (gi[base + 1024] + r * bhh[1024 + j]);
    ho[idx] = (1.f - z) * n;
}

// ---------------------------------------------------------------------------
// N=1 head: one warp per row.
// ---------------------------------------------------------------------------
__global__ void dot_k(const float* __restrict__ A, const float* __restrict__ w,
                      const float* __restrict__ bp, float* __restrict__ out)
{
    int g = blockIdx.x * blockDim.x + threadIdx.x;
    int row = g >> 5, lane = g & 31;
    const float4* a4 = reinterpret_cast<const float4*>(A + (size_t)row * HFD);
    const float4* w4 = reinterpret_cast<const float4*>(w);
    float s = 0.f;
#pragma unroll
    for (int i = lane; i < HFD / 4; i += 32) {
        float4 a = a4[i], b = w4[i];
        s += a.x * b.x + a.y * b.y + a.z * b.z + a.w * b.w;
    }
#pragma unroll
    for (int o = 16; o; o >>= 1) s += __shfl_xor_sync(0xffffffffu, s, o);
    if (lane == 0) out[row] = s + bp[0];
}

// ---------------------------------------------------------------------------
// Loss: deterministic 2-stage sum of squared residuals.
// ---------------------------------------------------------------------------
template<bool BCAST>
__global__ void reduce_sq_k(const float* __restrict__ x, const float* __restrict__ mu,
                            size_t n, float* __restrict__ part)
{
    float s = 0.f;
    for (size_t i = (size_t)blockIdx.x * blockDim.x + threadIdx.x; i < n;
         i += (size_t)gridDim.x * blockDim.x) {
        float m = BCAST ? mu[i >> 5] : mu[i];
        float d = x[i] - m;
        s += d * d;
    }
    __shared__ float sm[256];
    sm[threadIdx.x] = s; __syncthreads();
    for (int o = 128; o; o >>= 1) {
        if (threadIdx.x < o) sm[threadIdx.x] += sm[threadIdx.x + o];
        __syncthreads();
    }
    if (threadIdx.x == 0) part[blockIdx.x] = sm[0];
}

__global__ void finalize_k(const float* __restrict__ part, float* __restrict__ out)
{
    __shared__ double sm[256];
    double s = 0.0;
    for (int i = threadIdx.x; i < 3 * NBLK; i += 256) s += (double)part[i];
    sm[threadIdx.x] = s; __syncthreads();
    for (int o = 128; o; o >>= 1) {
        if (threadIdx.x < o) sm[threadIdx.x] += sm[threadIdx.x + o];
        __syncthreads();
    }
    if (threadIdx.x == 0) {
        const double LOG2PI = 1.8378770664093453;
        out[0] = (float)(0.5 * sm[0] / (double)(TT * BB)
                         + 0.5 * LOG2PI * (double)(OBSD + 2 * ACTD));
    }
}

// ---------------------------------------------------------------------------
extern "C" void kernel_launch(void* const* d_in, const int* in_sizes, int n_in,
                              void* d_out, int out_size)
{
    const float* obs    = (const float*)d_in[0];
    const float* action = (const float*)d_in[1];
    /* d_in[2] reward: unused by the reference math */
    const float* w_ih = (const float*)d_in[3];
    const float* w_hh = (const float*)d_in[4];
    const float* b_ih = (const float*)d_in[5];
    const float* b_hh = (const float*)d_in[6];
    const float* ow0 = (const float*)d_in[7],  *ob0 = (const float*)d_in[8];
    const float* ow1 = (const float*)d_in[9],  *ob1 = (const float*)d_in[10];
    const float* ow2 = (const float*)d_in[11], *ob2 = (const float*)d_in[12];
    const float* aw0 = (const float*)d_in[13], *ab0 = (const float*)d_in[14];
    const float* aw1 = (const float*)d_in[15], *ab1 = (const float*)d_in[16];
    const float* aw2 = (const float*)d_in[17], *ab2 = (const float*)d_in[18];
    const float* rw0 = (const float*)d_in[19], *rb0 = (const float*)d_in[20];
    const float* rw1 = (const float*)d_in[21], *rb1 = (const float*)d_in[22];
    const float* rw2 = (const float*)d_in[23], *rb2 = (const float*)d_in[24];

    float *GI, *GI0, *HS, *PART;
    cudaGetSymbolAddress((void**)&GI,   g_GI);
    cudaGetSymbolAddress((void**)&GI0,  g_GI0);
    cudaGetSymbolAddress((void**)&HS,   g_HS);
    cudaGetSymbolAddress((void**)&PART, g_part);
    // MLP scratch aliases the (dead after the recurrence) GI buffer.
    float* F1 = GI;
    float* F2 = GI + TBn * HFD;

    float* out      = (float*)d_out;
    float* pre_obs  = out + 1;
    float* pre_act  = pre_obs + TBn * OBSD;
    float* pre_rew  = pre_act + TBn * ACTD;

    // rnn dynamic smem: 96KB W + 64KB A-dup double buffer = 160KB
    const int rnn_smem = (3 * 512 * 16 + 2 * 64 * 128) * (int)sizeof(float);
    cudaFuncSetAttribute(rnn_k, cudaFuncAttributeMaxDynamicSharedMemorySize, rnn_smem);

    // 1) GI = [obs‖action] @ w_ih^T + b_ih   for all T*B rows
    sgemm_k<128, 128, 8, 8, 8, 0, true><<<dim3(G3D / 128, TBn / 128), 256>>>(
        obs, 0, action, w_ih, IND, b_ih, GI, G3D, IND);

    // 2) GI0 = obs[0] @ w_ih[:, :128]^T + b_ih  (action part of x0 is zero)
    sgemm_k<64, 64, 8, 4, 4, 0, false><<<dim3(G3D / 64, BB / 64), 256>>>(
        obs, OBSD, nullptr, w_ih, IND, b_ih, GI0, G3D, OBSD);

    // 3) h0 -> HS[0]  (also zeroes the rnn barrier counter)
    gate0_k<<<(BB * HIDD) / 256, 256>>>(GI0, b_hh, HS);

    // 4) recurrence: ONE persistent kernel, full-K slices, all 511 steps
    rnn_k<<<RNCTA, 256, rnn_smem>>>(w_hh, b_hh, GI, HS);

    dim3 gH(HFD / 128, TBn / 128);
    dim3 gO(OBSD / 128, TBn / 128);
    dim3 gA(ACTD / 32, TBn / 128);

    // 5) obs head
    sgemm_k<128, 128, 8, 8, 8, 1, false><<<gH, 256>>>(HS, HIDD, nullptr, ow0, HIDD, ob0, F1, HFD, HIDD);
    sgemm_k<128, 128, 8, 8, 8, 1, false><<<gH, 256>>>(F1, HFD, nullptr, ow1, HFD, ob1, F2, HFD, HFD);
    sgemm_k<128, 128, 8, 8, 8, 0, false><<<gO, 256>>>(F2, HFD, nullptr, ow2, HFD, ob2, pre_obs, OBSD, HFD);

    // 6) action head
    sgemm_k<128, 128, 8, 8, 8, 1, false><<<gH, 256>>>(HS, HIDD, nullptr, aw0, HIDD, ab0, F1, HFD, HIDD);
    sgemm_k<128, 128, 8, 8, 8, 1, false><<<gH, 256>>>(F1, HFD, nullptr, aw1, HFD, ab1, F2, HFD, HFD);
    sgemm_k<128, 32, 8, 8, 4, 0, false><<<gA, 128>>>(F2, HFD, nullptr, aw2, HFD, ab2, pre_act, ACTD, HFD);

    // 7) reward head
    sgemm_k<128, 128, 8, 8, 8, 1, false><<<gH, 256>>>(HS, HIDD, nullptr, rw0, HIDD, rb0, F1, HFD, HIDD);
    sgemm_k<128, 128, 8, 8, 8, 1, false><<<gH, 256>>>(F1, HFD, nullptr, rw1, HFD, rb1, F2, HFD, HFD);
    dot_k<<<TBn / 8, 256>>>(F2, rw2, rb2, pre_rew);

    // 8) losses (reward_loss faithfully reproduces the broadcast-vs-action bug)
    reduce_sq_k<false><<<NBLK, 256>>>(obs,    pre_obs, TBn * OBSD, PART);
    reduce_sq_k<false><<<NBLK, 256>>>(action, pre_act, TBn * ACTD, PART + NBLK);
    reduce_sq_k<true ><<<NBLK, 256>>>(action, pre_rew, TBn * ACTD, PART + 2 * NBLK);
    finalize_k<<<1, 256>>>(PART, out);
}

// round 17
// speedup vs baseline: 1.1224x; 1.0563x over previous
#include <cuda_runtime.h>
#include <math.h>

// Problem dims
#define TT   512
#define BB   256
#define OBSD 128
#define ACTD 32
#define IND  160
#define HIDD 512
#define G3D  1536
#define HFD  512

static constexpr size_t TBn = (size_t)TT * BB;      // 131072
static constexpr int NBLK = 2048;                    // reduction blocks per sum

// -------- scratch (static device globals; no runtime allocation) ----------
__device__ float g_GI [TBn * G3D];   // [T*B, 1536] input-gate preacts
__device__ float g_GI0[BB  * G3D];   // step-0 preacts
__device__ float g_HS [TBn * HIDD];  // emitted hidden states
__device__ float g_part[3 * NBLK];   // loss partials

// per-bg producer counters, padded 128B apart (zeroed by gate0_k each call)
__device__ unsigned g_bcnt[4 * 32];

__device__ __forceinline__ float4 ldg4(const float* p) {
    return *reinterpret_cast<const float4*>(p);
}
__device__ __forceinline__ float sigmoidf_(float x) { return 1.f / (1.f + expf(-x)); }

// ---- packed fp32x2 helpers ----
__device__ __forceinline__ unsigned long long pk2(float lo, float hi) {
    unsigned long long r;
    asm("mov.b64 %0, {%1, %2};" : "=l"(r) : "f"(lo), "f"(hi));
    return r;
}
__device__ __forceinline__ void fma2(unsigned long long& d,
                                     unsigned long long a, unsigned long long b) {
    asm("fma.rn.f32x2 %0, %1, %2, %0;" : "+l"(d) : "l"(a), "l"(b));
}
__device__ __forceinline__ float2 upk2(unsigned long long v) {
    float2 f;
    asm("mov.b64 {%0, %1}, %2;" : "=f"(f.x), "=f"(f.y) : "l"(v));
    return f;
}

// ---------------------------------------------------------------------------
// Generic tiled SGEMM with f32x2 inner loop (measured at the fp32 roofline).
// ---------------------------------------------------------------------------
template<int BM, int BN, int BK, int TM, int TN, int ACTMODE, bool CONCAT>
__global__ void __launch_bounds__((BM / TM) * (BN / TN))
sgemm_k(const float* __restrict__ A, int ldA,
        const float* __restrict__ A2,
        const float* __restrict__ W, int ldW,
        const float* __restrict__ bias,
        float* __restrict__ C, int ldC,
        int K)
{
    constexpr int NT = (BM / TM) * (BN / TN);
    constexpr int KQ = BK / 4;
    constexpr int TNP = TN / 2;

    __shared__ __align__(16) float As[BK][BM + 4];
    __shared__ __align__(16) float Ws[BK][BN + 4];

    const int tid = threadIdx.x;
    const int tx  = tid % (BN / TN);
    const int ty  = tid / (BN / TN);
    const int m0  = blockIdx.y * BM;
    const int n0  = blockIdx.x * BN;

    unsigned long long acc2[TM][TNP];
#pragma unroll
    for (int i = 0; i < TM; i++)
#pragma unroll
        for (int j = 0; j < TNP; j++) acc2[i][j] = 0ull;

    for (int k0 = 0; k0 < K; k0 += BK) {
        for (int i4 = tid; i4 < BM * KQ; i4 += NT) {
            int m = i4 / KQ, q = i4 % KQ;
            int kg = k0 + q * 4;
            float4 v;
            if (CONCAT) {
                if (kg < OBSD) v = ldg4(A  + (size_t)(m0 + m) * OBSD + kg);
                else           v = ldg4(A2 + (size_t)(m0 + m) * ACTD + (kg - OBSD));
            } else {
                v = ldg4(A + (size_t)(m0 + m) * ldA + kg);
            }
            As[q * 4 + 0][m] = v.x; As[q * 4 + 1][m] = v.y;
            As[q * 4 + 2][m] = v.z; As[q * 4 + 3][m] = v.w;
        }
        for (int i4 = tid; i4 < BN * KQ; i4 += NT) {
            int n = i4 / KQ, q = i4 % KQ;
            int kg = k0 + q * 4;
            float4 v = ldg4(W + (size_t)(n0 + n) * ldW + kg);
            Ws[q * 4 + 0][n] = v.x; Ws[q * 4 + 1][n] = v.y;
            Ws[q * 4 + 2][n] = v.z; Ws[q * 4 + 3][n] = v.w;
        }
        __syncthreads();

#pragma unroll
        for (int kk = 0; kk < BK; kk++) {
            float a[TM];
#pragma unroll
            for (int i = 0; i < TM; i += 4)
                *reinterpret_cast<float4*>(&a[i]) =
                    *reinterpret_cast<const float4*>(&As[kk][ty * TM + i]);
            unsigned long long b2[TNP];
#pragma unroll
            for (int j = 0; j < TNP; j += 2) {
                ulonglong2 t = *reinterpret_cast<const ulonglong2*>(&Ws[kk][tx * TN + 2 * j]);
                b2[j] = t.x; b2[j + 1] = t.y;
            }
#pragma unroll
            for (int i = 0; i < TM; i++) {
                unsigned long long ad = pk2(a[i], a[i]);
#pragma unroll
                for (int j = 0; j < TNP; j++) fma2(acc2[i][j], ad, b2[j]);
            }
        }
        __syncthreads();
    }

#pragma unroll
    for (int i = 0; i < TM; i++) {
        size_t m = (size_t)m0 + ty * TM + i;
#pragma unroll
        for (int j = 0; j < TNP; j++) {
            float2 v2 = upk2(acc2[i][j]);
            int n = n0 + tx * TN + 2 * j;
            float v = v2.x + bias[n];
            float w = v2.y + bias[n + 1];
            if (ACTMODE == 1) {
                v = (v > 0.f) ? v : expm1f(v);
                w = (w > 0.f) ? w : expm1f(w);
            }
            C[m * (size_t)ldC + n]     = v;
            C[m * (size_t)ldC + n + 1] = w;
        }
    }
}

// ---------------------------------------------------------------------------
// Persistent GRU recurrence v8: per-bg producer/consumer sync, no global
// barrier.  128 CTAs x 256 threads (1 CTA/SM, 2 warps/SMSP).
//   CTA: bg=blockIdx.x>>5 (4 independent groups of 64 rows),
//        cg=blockIdx.x&31 (32 x 16 cols).
//   W slice [3][512][16] = 96KB resident; A-dup chunks 2 x 32KB -> 160KB.
// Dependency: h_{t} rows of a bg are produced only by that bg's 32 CTAs.
//   Producers: after storing h_{t+1}: __syncthreads -> tid0 fence +
//   red.release.gpu.add(cnt[bg], 1)  (count reaches 32*(t+1)).
//   Consumers: at first use of h_t: per-warp lane0 ld.acquire.gpu poll for
//   cnt[bg] >= 32*t, then __syncwarp.  gi prefetch (t-indexed) issues BEFORE
//   the wait so its DRAM latency overlaps the poll.
// ---------------------------------------------------------------------------
#define RNCTA 128

__device__ __forceinline__ void rnn_ld_chunk(float4* R, const float* __restrict__ hp,
                                             int b0, int c, int tid)
{
#pragma unroll
    for (int p = 0; p < 4; p++) {
        int u = p * 256 + tid;
        int row = u & 63, q4 = u >> 6;               // 64 rows x 16 float4 (64 k)
        R[p] = ldg4(hp + (size_t)(b0 + row) * HIDD + c * 64 + q4 * 4);
    }
}

__device__ __forceinline__ void rnn_st_chunk(float* __restrict__ dst,
                                             const float4* R, int tid)
{
#pragma unroll
    for (int p = 0; p < 4; p++) {
        int u = p * 256 + tid;
        int row = u & 63, q4 = u >> 6;
        float4 v = R[p];
        *reinterpret_cast<float2*>(&dst[(q4 * 4 + 0) * 128 + 2 * row]) = make_float2(v.x, v.x);
        *reinterpret_cast<float2*>(&dst[(q4 * 4 + 1) * 128 + 2 * row]) = make_float2(v.y, v.y);
        *reinterpret_cast<float2*>(&dst[(q4 * 4 + 2) * 128 + 2 * row]) = make_float2(v.z, v.z);
        *reinterpret_cast<float2*>(&dst[(q4 * 4 + 3) * 128 + 2 * row]) = make_float2(v.w, v.w);
    }
}

__global__ void __launch_bounds__(256)
rnn_k(const float* __restrict__ w_hh, const float* __restrict__ b_hh,
      const float* __restrict__ gi_all, float* __restrict__ hs)
{
    extern __shared__ float sm[];
    float* Wsm  = sm;                    // [3][512][16] = 24576 floats (96KB)
    float* Abuf = sm + 3 * 512 * 16;     // 2 x [64k][128] = 16384 floats (64KB)

    const int tid  = threadIdx.x;
    const int lane = tid & 31;
    const int bg   = blockIdx.x >> 5;    // 4 independent groups x 64 rows
    const int cg   = blockIdx.x & 31;    // 32 groups x 16 cols
    const int b0   = bg * 64;
    const int j0   = cg * 16;
    const int tx   = tid & 7;            // 8 col-pairs (16 cols)
    const int ty   = tid >> 3;           // 32 row-pairs (64 rows)
    unsigned* cnt  = &g_bcnt[bg * 32];   // 128B-padded per-bg counter

    // one-time: W slice -> smem as [g][k][col] (16-col rows)
    for (int u = tid; u < 3 * 16 * 128; u += 256) {
        int g   = u >> 11;               // 0..2
        int r   = u & 2047;
        int col = r >> 7;                // 0..15
        int kq  = r & 127;               // k = 4*kq
        float4 v = ldg4(w_hh + (size_t)(g * HIDD + j0 + col) * HIDD + kq * 4);
        Wsm[(g * 512 + kq * 4 + 0) * 16 + col] = v.x;
        Wsm[(g * 512 + kq * 4 + 1) * 16 + col] = v.y;
        Wsm[(g * 512 + kq * 4 + 2) * 16 + col] = v.z;
        Wsm[(g * 512 + kq * 4 + 3) * 16 + col] = v.w;
    }
    const int jg = j0 + 2 * tx;
    const int r0 = b0 + 2 * ty;          // this thread's two batch rows
    const float2 br = *reinterpret_cast<const float2*>(b_hh + jg);
    const float2 bz = *reinterpret_cast<const float2*>(b_hh + 512 + jg);
    const float2 bn = *reinterpret_cast<const float2*>(b_hh + 1024 + jg);
    __syncthreads();

    for (int t = 0; t < TT - 1; t++) {
        const float* hp = hs + (size_t)t * BB * HIDD;
        float*       ho = hs + (size_t)(t + 1) * BB * HIDD;
        const float* gi = gi_all + (size_t)t * BB * G3D;

        // gi prefetch: t-indexed, independent of h -> issue BEFORE the wait
        float2 gr_[2], gz_[2], gn_[2], hp_[2];
#pragma unroll
        for (int i = 0; i < 2; i++) {
            const float* gim = gi + (size_t)(r0 + i) * G3D;
            gr_[i] = *reinterpret_cast<const float2*>(gim + jg);
            gz_[i] = *reinterpret_cast<const float2*>(gim + 512 + jg);
            gn_[i] = *reinterpret_cast<const float2*>(gim + 1024 + jg);
        }

        // wait for this bg's h_t producers (t=0: ready from gate0_k)
        if (t > 0) {
            if (lane == 0) {
                const unsigned target = 32u * (unsigned)t;
                unsigned v;
                while (true) {
                    asm volatile("ld.acquire.gpu.global.u32 %0, [%1];"
                                 : "=r"(v) : "l"(cnt) : "memory");
                    if (v >= target) break;
                    __nanosleep(20);
                }
            }
            __syncwarp();
        }

        // now safe to read h_t
#pragma unroll
        for (int i = 0; i < 2; i++)
            hp_[i] = *reinterpret_cast<const float2*>(
                hp + (size_t)(r0 + i) * HIDD + jg);

        unsigned long long aR[2] = {0,0}, aZ[2] = {0,0}, aN[2] = {0,0};

        // chunk 0: load regs -> store smem -> sync
        float4 Rs[4];
        rnn_ld_chunk(Rs, hp, b0, 0, tid);
        rnn_st_chunk(Abuf, Rs, tid);
        __syncthreads();

#pragma unroll 1
        for (int c = 0; c < 8; c++) {
            const float* Ac = Abuf + (c & 1) * 8192;
            if (c < 7) rnn_ld_chunk(Rs, hp, b0, c + 1, tid);

            const float* wR = &Wsm[(0 * 512 + c * 64) * 16 + 2 * tx];
            const float* wZ = &Wsm[(1 * 512 + c * 64) * 16 + 2 * tx];
            const float* wN = &Wsm[(2 * 512 + c * 64) * 16 + 2 * tx];
            const float* Ab = &Ac[4 * ty];

            ulonglong2        av[2];
            unsigned long long wr[2], wz[2], wn[2];
            av[0] = *reinterpret_cast<const ulonglong2*>(Ab);
            wr[0] = *reinterpret_cast<const unsigned long long*>(wR);
            wz[0] = *reinterpret_cast<const unsigned long long*>(wZ);
            wn[0] = *reinterpret_cast<const unsigned long long*>(wN);
            av[1] = *reinterpret_cast<const ulonglong2*>(Ab + 128);
            wr[1] = *reinterpret_cast<const unsigned long long*>(wR + 16);
            wz[1] = *reinterpret_cast<const unsigned long long*>(wZ + 16);
            wn[1] = *reinterpret_cast<const unsigned long long*>(wN + 16);
#pragma unroll
            for (int kk = 0; kk < 64; kk++) {
                const int cur = kk & 1;
                ulonglong2        a  = av[cur];
                unsigned long long r2 = wr[cur], z2 = wz[cur], n2 = wn[cur];
                if (kk < 62) {
                    av[cur] = *reinterpret_cast<const ulonglong2*>(Ab + (kk + 2) * 128);
                    wr[cur] = *reinterpret_cast<const unsigned long long*>(wR + (kk + 2) * 16);
                    wz[cur] = *reinterpret_cast<const unsigned long long*>(wZ + (kk + 2) * 16);
                    wn[cur] = *reinterpret_cast<const unsigned long long*>(wN + (kk + 2) * 16);
                }
                fma2(aR[0], a.x, r2); fma2(aR[1], a.y, r2);
                fma2(aZ[0], a.x, z2); fma2(aZ[1], a.y, z2);
                fma2(aN[0], a.x, n2); fma2(aN[1], a.y, n2);
            }

            if (c < 7) rnn_st_chunk(Abuf + ((c + 1) & 1) * 8192, Rs, tid);
            __syncthreads();
        }

        // gate math directly on accumulators; store 2 x float2 of h_{t+1}
#pragma unroll
        for (int i = 0; i < 2; i++) {
            float2 vr = upk2(aR[i]), vz = upk2(aZ[i]), vn = upk2(aN[i]);
            float rr0 = sigmoidf_(gr_[i].x + vr.x + br.x);
            float rr1 = sigmoidf_(gr_[i].y + vr.y + br.y);
            float zz0 = sigmoidf_(gz_[i].x + vz.x + bz.x);
            float zz1 = sigmoidf_(gz_[i].y + vz.y + bz.y);
            float nn0 = tanhf    (gn_[i].x + rr0 * (vn.x + bn.x));
            float nn1 = tanhf    (gn_[i].y + rr1 * (vn.y + bn.y));
            float2 hv;
            hv.x = (1.f - zz0) * nn0 + zz0 * hp_[i].x;
            hv.y = (1.f - zz1) * nn1 + zz1 * hp_[i].y;
            *reinterpret_cast<float2*>(ho + (size_t)(r0 + i) * HIDD + jg) = hv;
        }

        // arrival: all h_{t+1} stores done -> release-add on this bg's counter
        __syncthreads();
        if (tid == 0) {
            __threadfence();
            asm volatile("red.release.gpu.global.add.u32 [%0], %1;"
                         :: "l"(cnt), "r"(1u) : "memory");
        }
    }
}

// step 0: h_prev = 0  =>  gh = b_hh,  h0 = (1-z)*n.  Also zeroes the rnn
// sync counters (runs before rnn_k every call -> graph-replay safe).
__global__ void gate0_k(const float* __restrict__ gi, const float* __restrict__ bhh,
                        float* __restrict__ ho)
{
    if (blockIdx.x == 0 && threadIdx.x < 4 * 32) {
        g_bcnt[threadIdx.x] = 0u;
        __threadfence();
    }
    int idx = blockIdx.x * blockDim.x + threadIdx.x;
    int b = idx >> 9, j = idx & 511;
    size_t base = (size_t)b * G3D + j;
    float r = sigmoidf_(gi[base]        + bhh[j]);
    float z = sigmoidf_(gi[base + 512]  + bhh[512 + j]);
    float n = tanhf    (gi[base + 1024] + r * bhh[1024 + j]);
    ho[idx] = (1.f - z) * n;
}

// ---------------------------------------------------------------------------
// N=1 head: one warp per row.
// ---------------------------------------------------------------------------
__global__ void dot_k(const float* __restrict__ A, const float* __restrict__ w,
                      const float* __restrict__ bp, float* __restrict__ out)
{
    int g = blockIdx.x * blockDim.x + threadIdx.x;
    int row = g >> 5, lane = g & 31;
    const float4* a4 = reinterpret_cast<const float4*>(A + (size_t)row * HFD);
    const float4* w4 = reinterpret_cast<const float4*>(w);
    float s = 0.f;
#pragma unroll
    for (int i = lane; i < HFD / 4; i += 32) {
        float4 a = a4[i], b = w4[i];
        s += a.x * b.x + a.y * b.y + a.z * b.z + a.w * b.w;
    }
#pragma unroll
    for (int o = 16; o; o >>= 1) s += __shfl_xor_sync(0xffffffffu, s, o);
    if (lane == 0) out[row] = s + bp[0];
}

// ---------------------------------------------------------------------------
// Loss: deterministic 2-stage sum of squared residuals.
// ---------------------------------------------------------------------------
template<bool BCAST>
__global__ void reduce_sq_k(const float* __restrict__ x, const float* __restrict__ mu,
                            size_t n, float* __restrict__ part)
{
    float s = 0.f;
    for (size_t i = (size_t)blockIdx.x * blockDim.x + threadIdx.x; i < n;
         i += (size_t)gridDim.x * blockDim.x) {
        float m = BCAST ? mu[i >> 5] : mu[i];
        float d = x[i] - m;
        s += d * d;
    }
    __shared__ float sm[256];
    sm[threadIdx.x] = s; __syncthreads();
    for (int o = 128; o; o >>= 1) {
        if (threadIdx.x < o) sm[threadIdx.x] += sm[threadIdx.x + o];
        __syncthreads();
    }
    if (threadIdx.x == 0) part[blockIdx.x] = sm[0];
}

__global__ void finalize_k(const float* __restrict__ part, float* __restrict__ out)
{
    __shared__ double sm[256];
    double s = 0.0;
    for (int i = threadIdx.x; i < 3 * NBLK; i += 256) s += (double)part[i];
    sm[threadIdx.x] = s; __syncthreads();
    for (int o = 128; o; o >>= 1) {
        if (threadIdx.x < o) sm[threadIdx.x] += sm[threadIdx.x + o];
        __syncthreads();
    }
    if (threadIdx.x == 0) {
        const double LOG2PI = 1.8378770664093453;
        out[0] = (float)(0.5 * sm[0] / (double)(TT * BB)
                         + 0.5 * LOG2PI * (double)(OBSD + 2 * ACTD));
    }
}

// ---------------------------------------------------------------------------
extern "C" void kernel_launch(void* const* d_in, const int* in_sizes, int n_in,
                              void* d_out, int out_size)
{
    const float* obs    = (const float*)d_in[0];
    const float* action = (const float*)d_in[1];
    /* d_in[2] reward: unused by the reference math */
    const float* w_ih = (const float*)d_in[3];
    const float* w_hh = (const float*)d_in[4];
    const float* b_ih = (const float*)d_in[5];
    const float* b_hh = (const float*)d_in[6];
    const float* ow0 = (const float*)d_in[7],  *ob0 = (const float*)d_in[8];
    const float* ow1 = (const float*)d_in[9],  *ob1 = (const float*)d_in[10];
    const float* ow2 = (const float*)d_in[11], *ob2 = (const float*)d_in[12];
    const float* aw0 = (const float*)d_in[13], *ab0 = (const float*)d_in[14];
    const float* aw1 = (const float*)d_in[15], *ab1 = (const float*)d_in[16];
    const float* aw2 = (const float*)d_in[17], *ab2 = (const float*)d_in[18];
    const float* rw0 = (const float*)d_in[19], *rb0 = (const float*)d_in[20];
    const float* rw1 = (const float*)d_in[21], *rb1 = (const float*)d_in[22];
    const float* rw2 = (const float*)d_in[23], *rb2 = (const float*)d_in[24];

    float *GI, *GI0, *HS, *PART;
    cudaGetSymbolAddress((void**)&GI,   g_GI);
    cudaGetSymbolAddress((void**)&GI0,  g_GI0);
    cudaGetSymbolAddress((void**)&HS,   g_HS);
    cudaGetSymbolAddress((void**)&PART, g_part);
    // MLP scratch aliases the (dead after the recurrence) GI buffer.
    float* F1 = GI;
    float* F2 = GI + TBn * HFD;

    float* out      = (float*)d_out;
    float* pre_obs  = out + 1;
    float* pre_act  = pre_obs + TBn * OBSD;
    float* pre_rew  = pre_act + TBn * ACTD;

    // rnn dynamic smem: 96KB W + 64KB A-dup double buffer = 160KB
    const int rnn_smem = (3 * 512 * 16 + 2 * 64 * 128) * (int)sizeof(float);
    cudaFuncSetAttribute(rnn_k, cudaFuncAttributeMaxDynamicSharedMemorySize, rnn_smem);

    // 1) GI = [obs‖action] @ w_ih^T + b_ih   for all T*B rows
    sgemm_k<128, 128, 8, 8, 8, 0, true><<<dim3(G3D / 128, TBn / 128), 256>>>(
        obs, 0, action, w_ih, IND, b_ih, GI, G3D, IND);

    // 2) GI0 = obs[0] @ w_ih[:, :128]^T + b_ih  (action part of x0 is zero)
    sgemm_k<64, 64, 8, 4, 4, 0, false><<<dim3(G3D / 64, BB / 64), 256>>>(
        obs, OBSD, nullptr, w_ih, IND, b_ih, GI0, G3D, OBSD);

    // 3) h0 -> HS[0]  (also zeroes the rnn sync counters)
    gate0_k<<<(BB * HIDD) / 256, 256>>>(GI0, b_hh, HS);

    // 4) recurrence: ONE persistent kernel, per-bg producer/consumer sync
    rnn_k<<<RNCTA, 256, rnn_smem>>>(w_hh, b_hh, GI, HS);

    dim3 gH(HFD / 128, TBn / 128);
    dim3 gO(OBSD / 128, TBn / 128);
    dim3 gA(ACTD / 32, TBn / 128);

    // 5) obs head
    sgemm_k<128, 128, 8, 8, 8, 1, false><<<gH, 256>>>(HS, HIDD, nullptr, ow0, HIDD, ob0, F1, HFD, HIDD);
    sgemm_k<128, 128, 8, 8, 8, 1, false><<<gH, 256>>>(F1, HFD, nullptr, ow1, HFD, ob1, F2, HFD, HFD);
    sgemm_k<128, 128, 8, 8, 8, 0, false><<<gO, 256>>>(F2, HFD, nullptr, ow2, HFD, ob2, pre_obs, OBSD, HFD);

    // 6) action head
    sgemm_k<128, 128, 8, 8, 8, 1, false><<<gH, 256>>>(HS, HIDD, nullptr, aw0, HIDD, ab0, F1, HFD, HIDD);
    sgemm_k<128, 128, 8, 8, 8, 1, false><<<gH, 256>>>(F1, HFD, nullptr, aw1, HFD, ab1, F2, HFD, HFD);
    sgemm_k<128, 32, 8, 8, 4, 0, false><<<gA, 128>>>(F2, HFD, nullptr, aw2, HFD, ab2, pre_act, ACTD, HFD);

    // 7) reward head
    sgemm_k<128, 128, 8, 8, 8, 1, false><<<gH, 256>>>(HS, HIDD, nullptr, rw0, HIDD, rb0, F1, HFD, HIDD);
    sgemm_k<128, 128, 8, 8, 8, 1, false><<<gH, 256>>>(F1, HFD, nullptr, rw1, HFD, rb1, F2, HFD, HFD);
    dot_k<<<TBn / 8, 256>>>(F2, rw2, rb2, pre_rew);

    // 8) losses (reward_loss faithfully reproduces the broadcast-vs-action bug)
    reduce_sq_k<false><<<NBLK, 256>>>(obs,    pre_obs, TBn * OBSD, PART);
    reduce_sq_k<false><<<NBLK, 256>>>(action, pre_act, TBn * ACTD, PART + NBLK);
    reduce_sq_k<true ><<<NBLK, 256>>>(action, pre_rew, TBn * ACTD, PART + 2 * NBLK);
    finalize_k<<<1, 256>>>(PART, out);
}